// round 4
// baseline (speedup 1.0000x reference)
#include <cuda_runtime.h>
#include <math.h>

#define HIDDEN 2048
#define HEADS 16
#define HEAD_DIM 128
#define BATCH 2
#define SEQ 2048
#define MTOT (BATCH * SEQ)     // 4096
#define BH (BATCH * HEADS)     // 32

// ---------------- scratch (device globals; no allocations allowed) ----------
__device__ float g_q[MTOT * HIDDEN];
__device__ float g_k[MTOT * HIDDEN];
__device__ float g_v[MTOT * HIDDEN];
__device__ float g_ctx[MTOT * HIDDEN];
__device__ float g_sc[(size_t)BH * SEQ * SEQ];   // 512 MiB score/prob matrix

// ---------------------------------------------------------------------------
// Projection GEMM (128x64 tile, 8x4 micro-tile):
// C[M,N] = A[M,K] * W[N,K]^T ; M=4096, N=K=2048.
// ---------------------------------------------------------------------------
__global__ __launch_bounds__(256)
void gemm_proj(const float* __restrict__ A, const float* __restrict__ W,
               float* __restrict__ C) {
    __shared__ float As[16][128];
    __shared__ float Bs[16][64];

    const int tid = threadIdx.x;
    const int m0 = blockIdx.y * 128;
    const int n0 = blockIdx.x * 64;
    const int ty = tid >> 4, tx = tid & 15;          // 16x16 compute grid
    const int ar = tid >> 1, ak = (tid & 1) * 8;     // A: row 0..127, k base 0/8
    const int br = tid >> 2, bk = (tid & 3) * 4;     // W: row 0..63,  k base 0/4/8/12

    float acc[8][4];
#pragma unroll
    for (int i = 0; i < 8; i++)
#pragma unroll
        for (int j = 0; j < 4; j++) acc[i][j] = 0.f;

    for (int kt = 0; kt < HIDDEN; kt += 16) {
        float4 av0 = *(const float4*)&A[(size_t)(m0 + ar) * HIDDEN + kt + ak];
        float4 av1 = *(const float4*)&A[(size_t)(m0 + ar) * HIDDEN + kt + ak + 4];
        float4 bv  = *(const float4*)&W[(size_t)(n0 + br) * HIDDEN + kt + bk];
        __syncthreads();
        As[ak + 0][ar] = av0.x; As[ak + 1][ar] = av0.y;
        As[ak + 2][ar] = av0.z; As[ak + 3][ar] = av0.w;
        As[ak + 4][ar] = av1.x; As[ak + 5][ar] = av1.y;
        As[ak + 6][ar] = av1.z; As[ak + 7][ar] = av1.w;
        Bs[bk + 0][br] = bv.x; Bs[bk + 1][br] = bv.y;
        Bs[bk + 2][br] = bv.z; Bs[bk + 3][br] = bv.w;
        __syncthreads();
#pragma unroll
        for (int k = 0; k < 16; k++) {
            float a[8], b[4];
#pragma unroll
            for (int i = 0; i < 8; i++) a[i] = As[k][ty * 8 + i];
#pragma unroll
            for (int j = 0; j < 4; j++) b[j] = Bs[k][tx * 4 + j];
#pragma unroll
            for (int i = 0; i < 8; i++)
#pragma unroll
                for (int j = 0; j < 4; j++) acc[i][j] = fmaf(a[i], b[j], acc[i][j]);
        }
    }
#pragma unroll
    for (int i = 0; i < 8; i++) {
        int m = m0 + ty * 8 + i;
#pragma unroll
        for (int j = 0; j < 4; j++)
            C[(size_t)m * HIDDEN + n0 + tx * 4 + j] = acc[i][j];
    }
}

// ---------------------------------------------------------------------------
// RoPE, literal reference formula with double-precision trig.
// Row-major [MTOT, HIDDEN]; pair (h*128+d, h*128+d+64), d<64.
// ---------------------------------------------------------------------------
__global__ void rope2() {
    int idx = blockIdx.x * blockDim.x + threadIdx.x;  // row*1024 + h*64 + d
    if (idx >= MTOT * 1024) return;
    int d = idx & 63;
    int h = (idx >> 6) & 15;
    int row = idx >> 10;
    int s = row & (SEQ - 1);

    double inv = pow(10000.0, -((double)d) / 64.0);   // inv_freq[d]
    double ang = (double)s * inv;
    float c = (float)cos(ang);
    float sn = (float)sin(ang);

    size_t i1 = (size_t)row * HIDDEN + h * HEAD_DIM + d;
    float q1 = g_q[i1], q2 = g_q[i1 + 64];
    g_q[i1]      = q1 * c - q2 * sn;
    g_q[i1 + 64] = q2 * c + q1 * sn;
    float k1 = g_k[i1], k2 = g_k[i1 + 64];
    g_k[i1]      = k1 * c - k2 * sn;
    g_k[i1 + 64] = k2 * c + k1 * sn;
}

// ---------------------------------------------------------------------------
// Scores: S[bh][q][k] = (Q_h[q,:] . K_h[k,:]) * scale.  64x64 tiles, K-dim=128.
// Upper-triangle blocks (k0 > q0+63) are skipped (never read downstream).
// ---------------------------------------------------------------------------
__global__ __launch_bounds__(256)
void scores_qk() {
    const int k0 = blockIdx.x * 64;
    const int q0 = blockIdx.y * 64;
    if (k0 > q0 + 63) return;
    const int bh = blockIdx.z;
    const int b = bh >> 4, h = bh & 15;

    const float* Q = g_q + (size_t)b * SEQ * HIDDEN + h * HEAD_DIM;
    const float* K = g_k + (size_t)b * SEQ * HIDDEN + h * HEAD_DIM;
    float* S = g_sc + (size_t)bh * SEQ * SEQ;

    __shared__ float As[16][64];
    __shared__ float Bs[16][64];
    const int tid = threadIdx.x;
    const int ty = tid >> 4, tx = tid & 15;
    const int lr = tid >> 2, lk = (tid & 3) * 4;

    float acc[4][4];
#pragma unroll
    for (int i = 0; i < 4; i++)
#pragma unroll
        for (int j = 0; j < 4; j++) acc[i][j] = 0.f;

    for (int kt = 0; kt < HEAD_DIM; kt += 16) {
        float4 a  = *(const float4*)&Q[(size_t)(q0 + lr) * HIDDEN + kt + lk];
        float4 bb = *(const float4*)&K[(size_t)(k0 + lr) * HIDDEN + kt + lk];
        __syncthreads();
        As[lk + 0][lr] = a.x; As[lk + 1][lr] = a.y;
        As[lk + 2][lr] = a.z; As[lk + 3][lr] = a.w;
        Bs[lk + 0][lr] = bb.x; Bs[lk + 1][lr] = bb.y;
        Bs[lk + 2][lr] = bb.z; Bs[lk + 3][lr] = bb.w;
        __syncthreads();
#pragma unroll
        for (int k = 0; k < 16; k++) {
            float a4[4], b4[4];
#pragma unroll
            for (int i = 0; i < 4; i++) a4[i] = As[k][ty * 4 + i];
#pragma unroll
            for (int j = 0; j < 4; j++) b4[j] = Bs[k][tx * 4 + j];
#pragma unroll
            for (int i = 0; i < 4; i++)
#pragma unroll
                for (int j = 0; j < 4; j++) acc[i][j] = fmaf(a4[i], b4[j], acc[i][j]);
        }
    }
    const float scale = 0.08838834764831845f;  // 1/sqrt(128)
#pragma unroll
    for (int i = 0; i < 4; i++)
#pragma unroll
        for (int j = 0; j < 4; j++)
            S[(size_t)(q0 + ty * 4 + i) * SEQ + k0 + tx * 4 + j] = acc[i][j] * scale;
}

// ---------------------------------------------------------------------------
// Softmax per row over valid k in [0, q]; zeros for k > q.
// Two-pass (max, sum), smem tree reductions. One block per (bh, q).
// ---------------------------------------------------------------------------
__global__ __launch_bounds__(256)
void softmax_rows() {
    const int row = blockIdx.x;               // bh*SEQ + q
    const int q = row & (SEQ - 1);
    const int bh = row >> 11;
    float* P = g_sc + (size_t)bh * SEQ * SEQ + (size_t)q * SEQ;
    const int n = q + 1;
    const int tid = threadIdx.x;
    __shared__ float red[256];

    float mx = -1e30f;
    for (int j = tid; j < n; j += 256) mx = fmaxf(mx, P[j]);
    red[tid] = mx;
    __syncthreads();
    for (int s = 128; s > 0; s >>= 1) {
        if (tid < s) red[tid] = fmaxf(red[tid], red[tid + s]);
        __syncthreads();
    }
    float m = red[0];
    __syncthreads();

    float sum = 0.f;
    for (int j = tid; j < n; j += 256) sum += __expf(P[j] - m);
    red[tid] = sum;
    __syncthreads();
    for (int s = 128; s > 0; s >>= 1) {
        if (tid < s) red[tid] += red[tid + s];
        __syncthreads();
    }
    float inv = 1.0f / red[0];

    for (int j = tid; j < n; j += 256) P[j] = __expf(P[j] - m) * inv;
    for (int j = n + tid; j < SEQ; j += 256) P[j] = 0.f;
}

// ---------------------------------------------------------------------------
// PV: ctx_h[q, d] = sum_k P[q,k] * V_h[k, d].  NN GEMM, 64q x 128d tile.
// k loop bounded by q0+64 (P is zero beyond each row's q).
// ---------------------------------------------------------------------------
__global__ __launch_bounds__(256)
void pv_gemm() {
    const int q0 = blockIdx.x * 64;
    const int bh = blockIdx.y;
    const int b = bh >> 4, h = bh & 15;

    const float* P = g_sc + (size_t)bh * SEQ * SEQ;
    const float* V = g_v + (size_t)b * SEQ * HIDDEN + h * HEAD_DIM;
    float* O = g_ctx + (size_t)b * SEQ * HIDDEN + h * HEAD_DIM;

    __shared__ float Ps[64][17];
    __shared__ float Vs[16][128];
    const int tid = threadIdx.x;
    const int ty = tid >> 4, tx = tid & 15;
    const int pr = tid >> 2, pk = (tid & 3) * 4;   // P: row 0..63, k base
    const int vr = tid >> 4, vd = (tid & 15) * 8;  // V: k-row 0..15, d base

    float acc[4][8];
#pragma unroll
    for (int i = 0; i < 4; i++)
#pragma unroll
        for (int j = 0; j < 8; j++) acc[i][j] = 0.f;

    const int kmax = q0 + 64;   // <= SEQ
    for (int kt = 0; kt < kmax; kt += 16) {
        float4 p  = *(const float4*)&P[(size_t)(q0 + pr) * SEQ + kt + pk];
        float4 v0 = *(const float4*)&V[(size_t)(kt + vr) * HIDDEN + vd];
        float4 v1 = *(const float4*)&V[(size_t)(kt + vr) * HIDDEN + vd + 4];
        __syncthreads();
        Ps[pr][pk + 0] = p.x; Ps[pr][pk + 1] = p.y;
        Ps[pr][pk + 2] = p.z; Ps[pr][pk + 3] = p.w;
        *(float4*)&Vs[vr][vd]     = v0;
        *(float4*)&Vs[vr][vd + 4] = v1;
        __syncthreads();
#pragma unroll
        for (int k = 0; k < 16; k++) {
            float a4[4];
#pragma unroll
            for (int i = 0; i < 4; i++) a4[i] = Ps[ty * 4 + i][k];
            float4 bv0 = *(const float4*)&Vs[k][tx * 8];
            float4 bv1 = *(const float4*)&Vs[k][tx * 8 + 4];
            float b8[8] = {bv0.x, bv0.y, bv0.z, bv0.w, bv1.x, bv1.y, bv1.z, bv1.w};
#pragma unroll
            for (int i = 0; i < 4; i++)
#pragma unroll
                for (int j = 0; j < 8; j++) acc[i][j] = fmaf(a4[i], b8[j], acc[i][j]);
        }
    }
#pragma unroll
    for (int i = 0; i < 4; i++) {
        int qg = q0 + ty * 4 + i;
#pragma unroll
        for (int j = 0; j < 8; j++)
            O[(size_t)qg * HIDDEN + tx * 8 + j] = acc[i][j];
    }
}

// ---------------------------------------------------------------------------
extern "C" void kernel_launch(void* const* d_in, const int* in_sizes, int n_in,
                              void* d_out, int out_size) {
    // x identified by element count (8,388,608); weights keep relative order.
    int xi = 0;
    for (int i = 0; i < n_in; i++)
        if (in_sizes[i] == MTOT * HIDDEN) { xi = i; break; }

    const float* x;
    const float *Wq, *Wk, *Wv, *Wo;
    if (xi == 0) {
        x  = (const float*)d_in[0];
        Wq = (const float*)d_in[1];
        Wk = (const float*)d_in[2];
        Wv = (const float*)d_in[3];
        Wo = (const float*)d_in[4];
    } else {
        const float* w[4]; int j = 0;
        for (int i = 0; i < n_in; i++)
            if (i != xi) w[j++] = (const float*)d_in[i];
        x = (const float*)d_in[xi];
        Wk = w[0]; Wo = w[1]; Wq = w[2]; Wv = w[3];
    }

    float *qp, *kp, *vp, *cp;
    cudaGetSymbolAddress((void**)&qp, g_q);
    cudaGetSymbolAddress((void**)&kp, g_k);
    cudaGetSymbolAddress((void**)&vp, g_v);
    cudaGetSymbolAddress((void**)&cp, g_ctx);

    dim3 gp(HIDDEN / 64, MTOT / 128);          // (32, 32)
    gemm_proj<<<gp, 256>>>(x, Wq, qp);
    gemm_proj<<<gp, 256>>>(x, Wk, kp);
    gemm_proj<<<gp, 256>>>(x, Wv, vp);

    rope2<<<(MTOT * 1024 + 255) / 256, 256>>>();

    scores_qk<<<dim3(SEQ / 64, SEQ / 64, BH), 256>>>();
    softmax_rows<<<BH * SEQ, 256>>>();
    pv_gemm<<<dim3(SEQ / 64, BH), 256>>>();

    gemm_proj<<<gp, 256>>>(cp, Wo, (float*)d_out);
}

// round 5
// speedup vs baseline: 1.2261x; 1.2261x over previous
#include <cuda_runtime.h>
#include <math.h>
#include <stdint.h>

#define HIDDEN 2048
#define HEADS 16
#define HEAD_DIM 128
#define BATCH 2
#define SEQ 2048
#define MTOT (BATCH * SEQ)     // 4096
#define BH (BATCH * HEADS)     // 32

// ---------------- scratch (device globals; no allocations allowed) ----------
__device__ float g_q[MTOT * HIDDEN];
__device__ float g_k[MTOT * HIDDEN];
__device__ float g_v[MTOT * HIDDEN];
__device__ float g_ctx[MTOT * HIDDEN];
__device__ float g_sc[(size_t)BH * SEQ * SEQ];   // 512 MiB score/prob matrix

// ---------------------------------------------------------------------------
// tf32 helpers
// ---------------------------------------------------------------------------
__device__ __forceinline__ uint32_t f2tf32(float x) {
    uint32_t r;
    asm("cvt.rna.tf32.f32 %0, %1;" : "=r"(r) : "f"(x));
    return r;
}

__device__ __forceinline__ void mma_tf32(float* c, const uint32_t* a, const uint32_t* b) {
    asm("mma.sync.aligned.m16n8k8.row.col.f32.tf32.tf32.f32 "
        "{%0,%1,%2,%3}, {%4,%5,%6,%7}, {%8,%9}, {%0,%1,%2,%3};"
        : "+f"(c[0]), "+f"(c[1]), "+f"(c[2]), "+f"(c[3])
        : "r"(a[0]), "r"(a[1]), "r"(a[2]), "r"(a[3]), "r"(b[0]), "r"(b[1]));
}

// ---------------------------------------------------------------------------
// Split-tf32 (3xTF32) NT GEMM on tensor cores:
// C[M,N] = A[M,K] * W[N,K]^T ; M=4096, N=K=2048. Near-fp32 accuracy:
// A = Ah + Al, W = Bh + Bl ; C ~= Ah*Bh + Ah*Bl + Al*Bh  (Al*Bl dropped).
// Block 128x128, 8 warps as 2(m) x 4(n) of 64x32 warp tiles, KC=32.
// smem rows padded to 36 floats -> conflict-free fragment LDS.
// ---------------------------------------------------------------------------
#define KC 32
#define SROW 36
#define SM_TILE (128 * SROW)
#define GEMM_SMEM (4 * SM_TILE * 4)   // bytes: Ah, Al, Bh, Bl

__global__ __launch_bounds__(256, 2)
void gemm_tf32(const float* __restrict__ A, const float* __restrict__ W,
               float* __restrict__ C) {
    extern __shared__ __align__(16) float sm[];
    float* Ah = sm;
    float* Al = Ah + SM_TILE;
    float* Bh = Al + SM_TILE;
    float* Bl = Bh + SM_TILE;

    const int tid = threadIdx.x;
    const int warp = tid >> 5, lane = tid & 31;
    const int gid = lane >> 2, tq = lane & 3;     // quad row / thread-in-quad
    const int wm = (warp & 1) * 64;               // warp m-offset within block
    const int wn = (warp >> 1) * 32;              // warp n-offset within block
    const int m0 = blockIdx.y * 128, n0 = blockIdx.x * 128;

    const int lr = tid >> 1;                      // 0..127 (global load row)
    const int lc = (tid & 1) * 16;                // 0 / 16  (k base)

    float acc[4][4][4];
#pragma unroll
    for (int mt = 0; mt < 4; mt++)
#pragma unroll
        for (int nt = 0; nt < 4; nt++)
#pragma unroll
            for (int r = 0; r < 4; r++) acc[mt][nt][r] = 0.f;

    const float* Ap = A + (size_t)(m0 + lr) * HIDDEN + lc;
    const float* Wp = W + (size_t)(n0 + lr) * HIDDEN + lc;

    for (int kt = 0; kt < HIDDEN; kt += KC) {
        // ---- global loads (16 floats each from A and W) ----
        float4 av[4], wv[4];
#pragma unroll
        for (int i = 0; i < 4; i++) {
            av[i] = *(const float4*)(Ap + kt + 4 * i);
            wv[i] = *(const float4*)(Wp + kt + 4 * i);
        }
        __syncthreads();   // previous chunk's compute done
        // ---- split into tf32 hi/lo and stage ----
#pragma unroll
        for (int i = 0; i < 4; i++) {
            float a4[4] = {av[i].x, av[i].y, av[i].z, av[i].w};
            float w4[4] = {wv[i].x, wv[i].y, wv[i].z, wv[i].w};
            float ah4[4], al4[4], bh4[4], bl4[4];
#pragma unroll
            for (int j = 0; j < 4; j++) {
                uint32_t h = f2tf32(a4[j]);
                ah4[j] = __uint_as_float(h);
                al4[j] = __uint_as_float(f2tf32(a4[j] - __uint_as_float(h)));
                uint32_t g = f2tf32(w4[j]);
                bh4[j] = __uint_as_float(g);
                bl4[j] = __uint_as_float(f2tf32(w4[j] - __uint_as_float(g)));
            }
            int off = lr * SROW + lc + 4 * i;
            *(float4*)&Ah[off] = make_float4(ah4[0], ah4[1], ah4[2], ah4[3]);
            *(float4*)&Al[off] = make_float4(al4[0], al4[1], al4[2], al4[3]);
            *(float4*)&Bh[off] = make_float4(bh4[0], bh4[1], bh4[2], bh4[3]);
            *(float4*)&Bl[off] = make_float4(bl4[0], bl4[1], bl4[2], bl4[3]);
        }
        __syncthreads();

        // ---- compute: 4 k-steps of 8 ----
#pragma unroll
        for (int ks = 0; ks < 4; ks++) {
            const int kb = ks * 8;
            uint32_t bh[4][2], bl[4][2];
#pragma unroll
            for (int nt = 0; nt < 4; nt++) {
                int nr = (wn + nt * 8 + gid) * SROW + kb + tq;
                bh[nt][0] = __float_as_uint(Bh[nr]);
                bh[nt][1] = __float_as_uint(Bh[nr + 4]);
                bl[nt][0] = __float_as_uint(Bl[nr]);
                bl[nt][1] = __float_as_uint(Bl[nr + 4]);
            }
            uint32_t af[4][4];
#pragma unroll
            for (int mt = 0; mt < 4; mt++) {
                int r = (wm + mt * 16 + gid) * SROW + kb + tq;
                af[mt][0] = __float_as_uint(Ah[r]);
                af[mt][1] = __float_as_uint(Ah[r + 8 * SROW]);
                af[mt][2] = __float_as_uint(Ah[r + 4]);
                af[mt][3] = __float_as_uint(Ah[r + 8 * SROW + 4]);
            }
#pragma unroll
            for (int mt = 0; mt < 4; mt++)
#pragma unroll
                for (int nt = 0; nt < 4; nt++) {
                    mma_tf32(acc[mt][nt], af[mt], bh[nt]);   // hi*hi
                    mma_tf32(acc[mt][nt], af[mt], bl[nt]);   // hi*lo
                }
#pragma unroll
            for (int mt = 0; mt < 4; mt++) {
                int r = (wm + mt * 16 + gid) * SROW + kb + tq;
                af[mt][0] = __float_as_uint(Al[r]);
                af[mt][1] = __float_as_uint(Al[r + 8 * SROW]);
                af[mt][2] = __float_as_uint(Al[r + 4]);
                af[mt][3] = __float_as_uint(Al[r + 8 * SROW + 4]);
            }
#pragma unroll
            for (int mt = 0; mt < 4; mt++)
#pragma unroll
                for (int nt = 0; nt < 4; nt++)
                    mma_tf32(acc[mt][nt], af[mt], bh[nt]);   // lo*hi
        }
    }

    // ---- epilogue ----
#pragma unroll
    for (int mt = 0; mt < 4; mt++) {
        int row = m0 + wm + mt * 16 + gid;
#pragma unroll
        for (int nt = 0; nt < 4; nt++) {
            int col = n0 + wn + nt * 8 + 2 * tq;
            *(float2*)&C[(size_t)row * HIDDEN + col] =
                make_float2(acc[mt][nt][0], acc[mt][nt][1]);
            *(float2*)&C[(size_t)(row + 8) * HIDDEN + col] =
                make_float2(acc[mt][nt][2], acc[mt][nt][3]);
        }
    }
}

// ---------------------------------------------------------------------------
// RoPE, literal reference formula with double-precision trig.
// Row-major [MTOT, HIDDEN]; pair (h*128+d, h*128+d+64), d<64.
// ---------------------------------------------------------------------------
__global__ void rope2() {
    int idx = blockIdx.x * blockDim.x + threadIdx.x;  // row*1024 + h*64 + d
    if (idx >= MTOT * 1024) return;
    int d = idx & 63;
    int h = (idx >> 6) & 15;
    int row = idx >> 10;
    int s = row & (SEQ - 1);

    double inv = pow(10000.0, -((double)d) / 64.0);   // inv_freq[d]
    double ang = (double)s * inv;
    float c = (float)cos(ang);
    float sn = (float)sin(ang);

    size_t i1 = (size_t)row * HIDDEN + h * HEAD_DIM + d;
    float q1 = g_q[i1], q2 = g_q[i1 + 64];
    g_q[i1]      = q1 * c - q2 * sn;
    g_q[i1 + 64] = q2 * c + q1 * sn;
    float k1 = g_k[i1], k2 = g_k[i1 + 64];
    g_k[i1]      = k1 * c - k2 * sn;
    g_k[i1 + 64] = k2 * c + k1 * sn;
}

// ---------------------------------------------------------------------------
// Scores: S[bh][q][k] = (Q_h[q,:] . K_h[k,:]) * scale.  64x64 tiles, K-dim=128.
// Upper-triangle blocks (k0 > q0+63) are skipped (never read downstream).
// ---------------------------------------------------------------------------
__global__ __launch_bounds__(256)
void scores_qk() {
    const int k0 = blockIdx.x * 64;
    const int q0 = blockIdx.y * 64;
    if (k0 > q0 + 63) return;
    const int bh = blockIdx.z;
    const int b = bh >> 4, h = bh & 15;

    const float* Q = g_q + (size_t)b * SEQ * HIDDEN + h * HEAD_DIM;
    const float* K = g_k + (size_t)b * SEQ * HIDDEN + h * HEAD_DIM;
    float* S = g_sc + (size_t)bh * SEQ * SEQ;

    __shared__ float As[16][64];
    __shared__ float Bs[16][64];
    const int tid = threadIdx.x;
    const int ty = tid >> 4, tx = tid & 15;
    const int lr = tid >> 2, lk = (tid & 3) * 4;

    float acc[4][4];
#pragma unroll
    for (int i = 0; i < 4; i++)
#pragma unroll
        for (int j = 0; j < 4; j++) acc[i][j] = 0.f;

    for (int kt = 0; kt < HEAD_DIM; kt += 16) {
        float4 a  = *(const float4*)&Q[(size_t)(q0 + lr) * HIDDEN + kt + lk];
        float4 bb = *(const float4*)&K[(size_t)(k0 + lr) * HIDDEN + kt + lk];
        __syncthreads();
        As[lk + 0][lr] = a.x; As[lk + 1][lr] = a.y;
        As[lk + 2][lr] = a.z; As[lk + 3][lr] = a.w;
        Bs[lk + 0][lr] = bb.x; Bs[lk + 1][lr] = bb.y;
        Bs[lk + 2][lr] = bb.z; Bs[lk + 3][lr] = bb.w;
        __syncthreads();
#pragma unroll
        for (int k = 0; k < 16; k++) {
            float a4[4], b4[4];
#pragma unroll
            for (int i = 0; i < 4; i++) a4[i] = As[k][ty * 4 + i];
#pragma unroll
            for (int j = 0; j < 4; j++) b4[j] = Bs[k][tx * 4 + j];
#pragma unroll
            for (int i = 0; i < 4; i++)
#pragma unroll
                for (int j = 0; j < 4; j++) acc[i][j] = fmaf(a4[i], b4[j], acc[i][j]);
        }
    }
    const float scale = 0.08838834764831845f;  // 1/sqrt(128)
#pragma unroll
    for (int i = 0; i < 4; i++)
#pragma unroll
        for (int j = 0; j < 4; j++)
            S[(size_t)(q0 + ty * 4 + i) * SEQ + k0 + tx * 4 + j] = acc[i][j] * scale;
}

// ---------------------------------------------------------------------------
// Softmax per row over valid k in [0, q]; zeros for k > q.
// ---------------------------------------------------------------------------
__global__ __launch_bounds__(256)
void softmax_rows() {
    const int row = blockIdx.x;               // bh*SEQ + q
    const int q = row & (SEQ - 1);
    const int bh = row >> 11;
    float* P = g_sc + (size_t)bh * SEQ * SEQ + (size_t)q * SEQ;
    const int n = q + 1;
    const int tid = threadIdx.x;
    __shared__ float red[256];

    float mx = -1e30f;
    for (int j = tid; j < n; j += 256) mx = fmaxf(mx, P[j]);
    red[tid] = mx;
    __syncthreads();
    for (int s = 128; s > 0; s >>= 1) {
        if (tid < s) red[tid] = fmaxf(red[tid], red[tid + s]);
        __syncthreads();
    }
    float m = red[0];
    __syncthreads();

    float sum = 0.f;
    for (int j = tid; j < n; j += 256) sum += __expf(P[j] - m);
    red[tid] = sum;
    __syncthreads();
    for (int s = 128; s > 0; s >>= 1) {
        if (tid < s) red[tid] += red[tid + s];
        __syncthreads();
    }
    float inv = 1.0f / red[0];

    for (int j = tid; j < n; j += 256) P[j] = __expf(P[j] - m) * inv;
    for (int j = n + tid; j < SEQ; j += 256) P[j] = 0.f;
}

// ---------------------------------------------------------------------------
// PV: ctx_h[q, d] = sum_k P[q,k] * V_h[k, d].  NN GEMM, 64q x 128d tile.
// ---------------------------------------------------------------------------
__global__ __launch_bounds__(256)
void pv_gemm() {
    const int q0 = blockIdx.x * 64;
    const int bh = blockIdx.y;
    const int b = bh >> 4, h = bh & 15;

    const float* P = g_sc + (size_t)bh * SEQ * SEQ;
    const float* V = g_v + (size_t)b * SEQ * HIDDEN + h * HEAD_DIM;
    float* O = g_ctx + (size_t)b * SEQ * HIDDEN + h * HEAD_DIM;

    __shared__ float Ps[64][17];
    __shared__ float Vs[16][128];
    const int tid = threadIdx.x;
    const int ty = tid >> 4, tx = tid & 15;
    const int pr = tid >> 2, pk = (tid & 3) * 4;
    const int vr = tid >> 4, vd = (tid & 15) * 8;

    float acc[4][8];
#pragma unroll
    for (int i = 0; i < 4; i++)
#pragma unroll
        for (int j = 0; j < 8; j++) acc[i][j] = 0.f;

    const int kmax = q0 + 64;
    for (int kt = 0; kt < kmax; kt += 16) {
        float4 p  = *(const float4*)&P[(size_t)(q0 + pr) * SEQ + kt + pk];
        float4 v0 = *(const float4*)&V[(size_t)(kt + vr) * HIDDEN + vd];
        float4 v1 = *(const float4*)&V[(size_t)(kt + vr) * HIDDEN + vd + 4];
        __syncthreads();
        Ps[pr][pk + 0] = p.x; Ps[pr][pk + 1] = p.y;
        Ps[pr][pk + 2] = p.z; Ps[pr][pk + 3] = p.w;
        *(float4*)&Vs[vr][vd]     = v0;
        *(float4*)&Vs[vr][vd + 4] = v1;
        __syncthreads();
#pragma unroll
        for (int k = 0; k < 16; k++) {
            float a4[4];
#pragma unroll
            for (int i = 0; i < 4; i++) a4[i] = Ps[ty * 4 + i][k];
            float4 bv0 = *(const float4*)&Vs[k][tx * 8];
            float4 bv1 = *(const float4*)&Vs[k][tx * 8 + 4];
            float b8[8] = {bv0.x, bv0.y, bv0.z, bv0.w, bv1.x, bv1.y, bv1.z, bv1.w};
#pragma unroll
            for (int i = 0; i < 4; i++)
#pragma unroll
                for (int j = 0; j < 8; j++) acc[i][j] = fmaf(a4[i], b8[j], acc[i][j]);
        }
    }
#pragma unroll
    for (int i = 0; i < 4; i++) {
        int qg = q0 + ty * 4 + i;
#pragma unroll
        for (int j = 0; j < 8; j++)
            O[(size_t)qg * HIDDEN + tx * 8 + j] = acc[i][j];
    }
}

// ---------------------------------------------------------------------------
extern "C" void kernel_launch(void* const* d_in, const int* in_sizes, int n_in,
                              void* d_out, int out_size) {
    int xi = 0;
    for (int i = 0; i < n_in; i++)
        if (in_sizes[i] == MTOT * HIDDEN) { xi = i; break; }

    const float* x;
    const float *Wq, *Wk, *Wv, *Wo;
    if (xi == 0) {
        x  = (const float*)d_in[0];
        Wq = (const float*)d_in[1];
        Wk = (const float*)d_in[2];
        Wv = (const float*)d_in[3];
        Wo = (const float*)d_in[4];
    } else {
        const float* w[4]; int j = 0;
        for (int i = 0; i < n_in; i++)
            if (i != xi) w[j++] = (const float*)d_in[i];
        x = (const float*)d_in[xi];
        Wk = w[0]; Wo = w[1]; Wq = w[2]; Wv = w[3];
    }

    float *qp, *kp, *vp, *cp;
    cudaGetSymbolAddress((void**)&qp, g_q);
    cudaGetSymbolAddress((void**)&kp, g_k);
    cudaGetSymbolAddress((void**)&vp, g_v);
    cudaGetSymbolAddress((void**)&cp, g_ctx);

    cudaFuncSetAttribute(gemm_tf32,
                         cudaFuncAttributeMaxDynamicSharedMemorySize, GEMM_SMEM);

    dim3 gg(HIDDEN / 128, MTOT / 128);   // (16, 32)
    gemm_tf32<<<gg, 256, GEMM_SMEM>>>(x, Wq, qp);
    gemm_tf32<<<gg, 256, GEMM_SMEM>>>(x, Wk, kp);
    gemm_tf32<<<gg, 256, GEMM_SMEM>>>(x, Wv, vp);

    rope2<<<(MTOT * 1024 + 255) / 256, 256>>>();

    scores_qk<<<dim3(SEQ / 64, SEQ / 64, BH), 256>>>();
    softmax_rows<<<BH * SEQ, 256>>>();
    pv_gemm<<<dim3(SEQ / 64, BH), 256>>>();

    gemm_tf32<<<gg, 256, GEMM_SMEM>>>(cp, Wo, (float*)d_out);
}

// round 6
// speedup vs baseline: 1.3835x; 1.1284x over previous
#include <cuda_runtime.h>
#include <math.h>
#include <stdint.h>

#define HIDDEN 2048
#define HEADS 16
#define HEAD_DIM 128
#define BATCH 2
#define SEQ 2048
#define MTOT (BATCH * SEQ)     // 4096
#define BH (BATCH * HEADS)     // 32

// ---------------- scratch (device globals; no allocations allowed) ----------
__device__ float g_q[MTOT * HIDDEN];
__device__ float g_k[MTOT * HIDDEN];
__device__ float g_v[MTOT * HIDDEN];
__device__ float g_ctx[MTOT * HIDDEN];
__device__ float g_sc[(size_t)BH * SEQ * SEQ];   // 512 MiB score/prob matrix

// ---------------------------------------------------------------------------
// tf32 helpers
// ---------------------------------------------------------------------------
__device__ __forceinline__ uint32_t f2tf32(float x) {
    uint32_t r;
    asm("cvt.rna.tf32.f32 %0, %1;" : "=r"(r) : "f"(x));
    return r;
}

__device__ __forceinline__ void mma_tf32(float* c, const uint32_t* a, const uint32_t* b) {
    asm("mma.sync.aligned.m16n8k8.row.col.f32.tf32.tf32.f32 "
        "{%0,%1,%2,%3}, {%4,%5,%6,%7}, {%8,%9}, {%0,%1,%2,%3};"
        : "+f"(c[0]), "+f"(c[1]), "+f"(c[2]), "+f"(c[3])
        : "r"(a[0]), "r"(a[1]), "r"(a[2]), "r"(a[3]), "r"(b[0]), "r"(b[1]));
}

#define KC 32
#define SROW 36
#define SM_TILE (128 * SROW)
#define GEMM_SMEM (4 * SM_TILE * 4)   // bytes: Ah, Al, Bh, Bl

// Shared compute core: one KC-chunk of 3xTF32 mma on staged hi/lo tiles.
__device__ __forceinline__ void mma_chunk(
    const float* Ah, const float* Al, const float* Bh, const float* Bl,
    int wm, int wn, int gid, int tq, float acc[4][4][4]) {
#pragma unroll
    for (int ks = 0; ks < 4; ks++) {
        const int kb = ks * 8;
        uint32_t bh[4][2], bl[4][2];
#pragma unroll
        for (int nt = 0; nt < 4; nt++) {
            int nr = (wn + nt * 8 + gid) * SROW + kb + tq;
            bh[nt][0] = __float_as_uint(Bh[nr]);
            bh[nt][1] = __float_as_uint(Bh[nr + 4]);
            bl[nt][0] = __float_as_uint(Bl[nr]);
            bl[nt][1] = __float_as_uint(Bl[nr + 4]);
        }
        uint32_t af[4][4];
#pragma unroll
        for (int mt = 0; mt < 4; mt++) {
            int r = (wm + mt * 16 + gid) * SROW + kb + tq;
            af[mt][0] = __float_as_uint(Ah[r]);
            af[mt][1] = __float_as_uint(Ah[r + 8 * SROW]);
            af[mt][2] = __float_as_uint(Ah[r + 4]);
            af[mt][3] = __float_as_uint(Ah[r + 8 * SROW + 4]);
        }
#pragma unroll
        for (int mt = 0; mt < 4; mt++)
#pragma unroll
            for (int nt = 0; nt < 4; nt++) {
                mma_tf32(acc[mt][nt], af[mt], bh[nt]);   // hi*hi
                mma_tf32(acc[mt][nt], af[mt], bl[nt]);   // hi*lo
            }
#pragma unroll
        for (int mt = 0; mt < 4; mt++) {
            int r = (wm + mt * 16 + gid) * SROW + kb + tq;
            af[mt][0] = __float_as_uint(Al[r]);
            af[mt][1] = __float_as_uint(Al[r + 8 * SROW]);
            af[mt][2] = __float_as_uint(Al[r + 4]);
            af[mt][3] = __float_as_uint(Al[r + 8 * SROW + 4]);
        }
#pragma unroll
        for (int mt = 0; mt < 4; mt++)
#pragma unroll
            for (int nt = 0; nt < 4; nt++)
                mma_tf32(acc[mt][nt], af[mt], bh[nt]);   // lo*hi
    }
}

__device__ __forceinline__ void split_store(float v, float* hi, float* lo, int off) {
    uint32_t h = f2tf32(v);
    hi[off] = __uint_as_float(h);
    lo[off] = __uint_as_float(f2tf32(v - __uint_as_float(h)));
}

// ---------------------------------------------------------------------------
// Split-tf32 NT GEMM: C[M,N] = A[M,K] * W[N,K]^T ; M=4096, N=K=2048.
// Block 128x128, 8 warps (2m x 4n of 64x32 warp tiles), KC=32.
// ---------------------------------------------------------------------------
__global__ __launch_bounds__(256, 2)
void gemm_tf32(const float* __restrict__ A, const float* __restrict__ W,
               float* __restrict__ C) {
    extern __shared__ __align__(16) float sm[];
    float* Ah = sm;
    float* Al = Ah + SM_TILE;
    float* Bh = Al + SM_TILE;
    float* Bl = Bh + SM_TILE;

    const int tid = threadIdx.x;
    const int warp = tid >> 5, lane = tid & 31;
    const int gid = lane >> 2, tq = lane & 3;
    const int wm = (warp & 1) * 64;
    const int wn = (warp >> 1) * 32;
    const int m0 = blockIdx.y * 128, n0 = blockIdx.x * 128;
    const int lr = tid >> 1;
    const int lc = (tid & 1) * 16;

    float acc[4][4][4];
#pragma unroll
    for (int mt = 0; mt < 4; mt++)
#pragma unroll
        for (int nt = 0; nt < 4; nt++)
#pragma unroll
            for (int r = 0; r < 4; r++) acc[mt][nt][r] = 0.f;

    const float* Ap = A + (size_t)(m0 + lr) * HIDDEN + lc;
    const float* Wp = W + (size_t)(n0 + lr) * HIDDEN + lc;

    for (int kt = 0; kt < HIDDEN; kt += KC) {
        float4 av[4], wv[4];
#pragma unroll
        for (int i = 0; i < 4; i++) {
            av[i] = *(const float4*)(Ap + kt + 4 * i);
            wv[i] = *(const float4*)(Wp + kt + 4 * i);
        }
        __syncthreads();
#pragma unroll
        for (int i = 0; i < 4; i++) {
            int off = lr * SROW + lc + 4 * i;
            split_store(av[i].x, Ah, Al, off + 0);
            split_store(av[i].y, Ah, Al, off + 1);
            split_store(av[i].z, Ah, Al, off + 2);
            split_store(av[i].w, Ah, Al, off + 3);
            split_store(wv[i].x, Bh, Bl, off + 0);
            split_store(wv[i].y, Bh, Bl, off + 1);
            split_store(wv[i].z, Bh, Bl, off + 2);
            split_store(wv[i].w, Bh, Bl, off + 3);
        }
        __syncthreads();
        mma_chunk(Ah, Al, Bh, Bl, wm, wn, gid, tq, acc);
    }

#pragma unroll
    for (int mt = 0; mt < 4; mt++) {
        int row = m0 + wm + mt * 16 + gid;
#pragma unroll
        for (int nt = 0; nt < 4; nt++) {
            int col = n0 + wn + nt * 8 + 2 * tq;
            *(float2*)&C[(size_t)row * HIDDEN + col] =
                make_float2(acc[mt][nt][0], acc[mt][nt][1]);
            *(float2*)&C[(size_t)(row + 8) * HIDDEN + col] =
                make_float2(acc[mt][nt][2], acc[mt][nt][3]);
        }
    }
}

// ---------------------------------------------------------------------------
// Scores on tensor cores: S[bh] = (Q_h . K_h^T) * scale, 128x128 tiles,
// lower-triangle blocks only (k0 <= q0). K-loop = HEAD_DIM (4 chunks).
// ---------------------------------------------------------------------------
__global__ __launch_bounds__(256, 2)
void scores_tf32() {
    const int k0 = blockIdx.x * 128;
    const int q0 = blockIdx.y * 128;
    if (k0 > q0) return;
    const int bh = blockIdx.z;
    const int b = bh >> 4, h = bh & 15;

    extern __shared__ __align__(16) float sm[];
    float* Ah = sm;
    float* Al = Ah + SM_TILE;
    float* Bh = Al + SM_TILE;
    float* Bl = Bh + SM_TILE;

    const int tid = threadIdx.x;
    const int warp = tid >> 5, lane = tid & 31;
    const int gid = lane >> 2, tq = lane & 3;
    const int wm = (warp & 1) * 64;
    const int wn = (warp >> 1) * 32;
    const int lr = tid >> 1;
    const int lc = (tid & 1) * 16;

    const float* Q = g_q + (size_t)b * SEQ * HIDDEN + h * HEAD_DIM;
    const float* K = g_k + (size_t)b * SEQ * HIDDEN + h * HEAD_DIM;
    float* S = g_sc + (size_t)bh * SEQ * SEQ;

    float acc[4][4][4];
#pragma unroll
    for (int mt = 0; mt < 4; mt++)
#pragma unroll
        for (int nt = 0; nt < 4; nt++)
#pragma unroll
            for (int r = 0; r < 4; r++) acc[mt][nt][r] = 0.f;

    const float* Qp = Q + (size_t)(q0 + lr) * HIDDEN + lc;
    const float* Kp = K + (size_t)(k0 + lr) * HIDDEN + lc;

#pragma unroll
    for (int kt = 0; kt < HEAD_DIM; kt += KC) {
        float4 av[4], wv[4];
#pragma unroll
        for (int i = 0; i < 4; i++) {
            av[i] = *(const float4*)(Qp + kt + 4 * i);
            wv[i] = *(const float4*)(Kp + kt + 4 * i);
        }
        __syncthreads();
#pragma unroll
        for (int i = 0; i < 4; i++) {
            int off = lr * SROW + lc + 4 * i;
            split_store(av[i].x, Ah, Al, off + 0);
            split_store(av[i].y, Ah, Al, off + 1);
            split_store(av[i].z, Ah, Al, off + 2);
            split_store(av[i].w, Ah, Al, off + 3);
            split_store(wv[i].x, Bh, Bl, off + 0);
            split_store(wv[i].y, Bh, Bl, off + 1);
            split_store(wv[i].z, Bh, Bl, off + 2);
            split_store(wv[i].w, Bh, Bl, off + 3);
        }
        __syncthreads();
        mma_chunk(Ah, Al, Bh, Bl, wm, wn, gid, tq, acc);
    }

    const float scale = 0.08838834764831845f;  // 1/sqrt(128)
#pragma unroll
    for (int mt = 0; mt < 4; mt++) {
        int row = q0 + wm + mt * 16 + gid;
#pragma unroll
        for (int nt = 0; nt < 4; nt++) {
            int col = k0 + wn + nt * 8 + 2 * tq;
            *(float2*)&S[(size_t)row * SEQ + col] =
                make_float2(acc[mt][nt][0] * scale, acc[mt][nt][1] * scale);
            *(float2*)&S[(size_t)(row + 8) * SEQ + col] =
                make_float2(acc[mt][nt][2] * scale, acc[mt][nt][3] * scale);
        }
    }
}

// ---------------------------------------------------------------------------
// PV on tensor cores: ctx_h[q,d] = sum_k P[q,k] V_h[k,d]. 128q x 128d block.
// V staged transposed (Bs[d][k]) to fit mma's NT orientation.
// k-loop bounded at q0+128; P is zero beyond each row's diagonal.
// ---------------------------------------------------------------------------
__global__ __launch_bounds__(256, 2)
void pv_tf32() {
    const int q0 = blockIdx.x * 128;
    const int bh = blockIdx.y;
    const int b = bh >> 4, h = bh & 15;

    extern __shared__ __align__(16) float sm[];
    float* Ah = sm;
    float* Al = Ah + SM_TILE;
    float* Bh = Al + SM_TILE;
    float* Bl = Bh + SM_TILE;

    const int tid = threadIdx.x;
    const int warp = tid >> 5, lane = tid & 31;
    const int gid = lane >> 2, tq = lane & 3;
    const int wm = (warp & 1) * 64;
    const int wn = (warp >> 1) * 32;
    const int lr = tid >> 1;
    const int lc = (tid & 1) * 16;
    const int vr = tid >> 3;            // 0..31 (k row within chunk)
    const int vd = (tid & 7) * 16;      // d base: 0..112

    const float* P = g_sc + (size_t)bh * SEQ * SEQ;
    const float* V = g_v + (size_t)b * SEQ * HIDDEN + h * HEAD_DIM;
    float* O = g_ctx + (size_t)b * SEQ * HIDDEN + h * HEAD_DIM;

    float acc[4][4][4];
#pragma unroll
    for (int mt = 0; mt < 4; mt++)
#pragma unroll
        for (int nt = 0; nt < 4; nt++)
#pragma unroll
            for (int r = 0; r < 4; r++) acc[mt][nt][r] = 0.f;

    const int kmax = q0 + 128;
    for (int kt = 0; kt < kmax; kt += KC) {
        float4 pv4[4], vv[4];
#pragma unroll
        for (int i = 0; i < 4; i++) {
            pv4[i] = *(const float4*)&P[(size_t)(q0 + lr) * SEQ + kt + lc + 4 * i];
            vv[i]  = *(const float4*)&V[(size_t)(kt + vr) * HIDDEN + vd + 4 * i];
        }
        __syncthreads();
#pragma unroll
        for (int i = 0; i < 4; i++) {
            int off = lr * SROW + lc + 4 * i;
            split_store(pv4[i].x, Ah, Al, off + 0);
            split_store(pv4[i].y, Ah, Al, off + 1);
            split_store(pv4[i].z, Ah, Al, off + 2);
            split_store(pv4[i].w, Ah, Al, off + 3);
            // V transposed: Bs[d][k]
            split_store(vv[i].x, Bh, Bl, (vd + 4 * i + 0) * SROW + vr);
            split_store(vv[i].y, Bh, Bl, (vd + 4 * i + 1) * SROW + vr);
            split_store(vv[i].z, Bh, Bl, (vd + 4 * i + 2) * SROW + vr);
            split_store(vv[i].w, Bh, Bl, (vd + 4 * i + 3) * SROW + vr);
        }
        __syncthreads();
        mma_chunk(Ah, Al, Bh, Bl, wm, wn, gid, tq, acc);
    }

#pragma unroll
    for (int mt = 0; mt < 4; mt++) {
        int row = q0 + wm + mt * 16 + gid;
#pragma unroll
        for (int nt = 0; nt < 4; nt++) {
            int col = wn + nt * 8 + 2 * tq;
            *(float2*)&O[(size_t)row * HIDDEN + col] =
                make_float2(acc[mt][nt][0], acc[mt][nt][1]);
            *(float2*)&O[(size_t)(row + 8) * HIDDEN + col] =
                make_float2(acc[mt][nt][2], acc[mt][nt][3]);
        }
    }
}

// ---------------------------------------------------------------------------
// RoPE (unchanged, proven).
// ---------------------------------------------------------------------------
__global__ void rope2() {
    int idx = blockIdx.x * blockDim.x + threadIdx.x;
    if (idx >= MTOT * 1024) return;
    int d = idx & 63;
    int h = (idx >> 6) & 15;
    int row = idx >> 10;
    int s = row & (SEQ - 1);

    double inv = pow(10000.0, -((double)d) / 64.0);
    double ang = (double)s * inv;
    float c = (float)cos(ang);
    float sn = (float)sin(ang);

    size_t i1 = (size_t)row * HIDDEN + h * HEAD_DIM + d;
    float q1 = g_q[i1], q2 = g_q[i1 + 64];
    g_q[i1]      = q1 * c - q2 * sn;
    g_q[i1 + 64] = q2 * c + q1 * sn;
    float k1 = g_k[i1], k2 = g_k[i1 + 64];
    g_k[i1]      = k1 * c - k2 * sn;
    g_k[i1 + 64] = k2 * c + k1 * sn;
}

// ---------------------------------------------------------------------------
// Softmax per row over valid k in [0, q]; zeros for k > q (unchanged, proven).
// ---------------------------------------------------------------------------
__global__ __launch_bounds__(256)
void softmax_rows() {
    const int row = blockIdx.x;
    const int q = row & (SEQ - 1);
    const int bh = row >> 11;
    float* P = g_sc + (size_t)bh * SEQ * SEQ + (size_t)q * SEQ;
    const int n = q + 1;
    const int tid = threadIdx.x;
    __shared__ float red[256];

    float mx = -1e30f;
    for (int j = tid; j < n; j += 256) mx = fmaxf(mx, P[j]);
    red[tid] = mx;
    __syncthreads();
    for (int s = 128; s > 0; s >>= 1) {
        if (tid < s) red[tid] = fmaxf(red[tid], red[tid + s]);
        __syncthreads();
    }
    float m = red[0];
    __syncthreads();

    float sum = 0.f;
    for (int j = tid; j < n; j += 256) sum += __expf(P[j] - m);
    red[tid] = sum;
    __syncthreads();
    for (int s = 128; s > 0; s >>= 1) {
        if (tid < s) red[tid] += red[tid + s];
        __syncthreads();
    }
    float inv = 1.0f / red[0];

    for (int j = tid; j < n; j += 256) P[j] = __expf(P[j] - m) * inv;
    for (int j = n + tid; j < SEQ; j += 256) P[j] = 0.f;
}

// ---------------------------------------------------------------------------
extern "C" void kernel_launch(void* const* d_in, const int* in_sizes, int n_in,
                              void* d_out, int out_size) {
    int xi = 0;
    for (int i = 0; i < n_in; i++)
        if (in_sizes[i] == MTOT * HIDDEN) { xi = i; break; }

    const float* x;
    const float *Wq, *Wk, *Wv, *Wo;
    if (xi == 0) {
        x  = (const float*)d_in[0];
        Wq = (const float*)d_in[1];
        Wk = (const float*)d_in[2];
        Wv = (const float*)d_in[3];
        Wo = (const float*)d_in[4];
    } else {
        const float* w[4]; int j = 0;
        for (int i = 0; i < n_in; i++)
            if (i != xi) w[j++] = (const float*)d_in[i];
        x = (const float*)d_in[xi];
        Wk = w[0]; Wo = w[1]; Wq = w[2]; Wv = w[3];
    }

    float *qp, *kp, *vp, *cp;
    cudaGetSymbolAddress((void**)&qp, g_q);
    cudaGetSymbolAddress((void**)&kp, g_k);
    cudaGetSymbolAddress((void**)&vp, g_v);
    cudaGetSymbolAddress((void**)&cp, g_ctx);

    cudaFuncSetAttribute(gemm_tf32,
                         cudaFuncAttributeMaxDynamicSharedMemorySize, GEMM_SMEM);
    cudaFuncSetAttribute(scores_tf32,
                         cudaFuncAttributeMaxDynamicSharedMemorySize, GEMM_SMEM);
    cudaFuncSetAttribute(pv_tf32,
                         cudaFuncAttributeMaxDynamicSharedMemorySize, GEMM_SMEM);

    dim3 gg(HIDDEN / 128, MTOT / 128);   // (16, 32)
    gemm_tf32<<<gg, 256, GEMM_SMEM>>>(x, Wq, qp);
    gemm_tf32<<<gg, 256, GEMM_SMEM>>>(x, Wk, kp);
    gemm_tf32<<<gg, 256, GEMM_SMEM>>>(x, Wv, vp);

    rope2<<<(MTOT * 1024 + 255) / 256, 256>>>();

    scores_tf32<<<dim3(SEQ / 128, SEQ / 128, BH), 256, GEMM_SMEM>>>();
    softmax_rows<<<BH * SEQ, 256>>>();
    pv_tf32<<<dim3(SEQ / 128, BH), 256, GEMM_SMEM>>>();

    gemm_tf32<<<gg, 256, GEMM_SMEM>>>(cp, Wo, (float*)d_out);
}